// round 4
// baseline (speedup 1.0000x reference)
#include <cuda_runtime.h>
#include <math.h>

#define HW 65536
#define WID 256
#define HGT 256

// Scratch (no allocations allowed)
__device__ float g_h0[2 * 48 * HW];
__device__ float g_h1[2 * 48 * HW];
__device__ float g_ab[2 * 24 * HW];   // batch0 = a, batch1 = b
__device__ float g_Q[24 * HW];
__device__ float g_K[24 * HW];
__device__ float g_V[24 * HW];

// ---------------------------------------------------------------------------
// Direct 3x3 conv, NCHW, pad=1. One thread per output pixel, all COUT
// accumulators in registers. Weights staged to smem transposed to
// [cin*9][cout] so the inner loop is broadcast LDS.128.
// grid = (256 rows, 2 batches), block = 256 threads (one row of x).
// ---------------------------------------------------------------------------
template <int CIN, int COUT, bool RELU, bool SKIP>
__global__ void __launch_bounds__(256, 2) conv3x3_kernel(
    const float* __restrict__ in, const float* __restrict__ w,
    const float* __restrict__ bias, float* __restrict__ out,
    long in_bstride, long out_bstride,
    const float* __restrict__ skip_in, long skip_bstride,
    const float* __restrict__ skip_w, const float* __restrict__ skip_b)
{
    extern __shared__ float smem[];
    float* ws = smem;                 // [CIN*9][COUT]
    float* bs = ws + CIN * 9 * COUT;  // [COUT]
    float* sw = bs + COUT;            // [3][COUT] (skip weights, transposed)
    float* sb = sw + (SKIP ? 3 * COUT : 0);

    for (int i = threadIdx.x; i < CIN * 9 * COUT; i += 256) {
        int co = i % COUT;
        int r  = i / COUT;
        int ci = r / 9;
        int k  = r % 9;
        ws[i] = w[(co * CIN + ci) * 9 + k];
    }
    if (threadIdx.x < COUT) bs[threadIdx.x] = bias[threadIdx.x];
    if (SKIP) {
        for (int i = threadIdx.x; i < 3 * COUT; i += 256) {
            int co = i % COUT;
            int ci = i / COUT;
            sw[i] = skip_w[co * 3 + ci];
        }
        if (threadIdx.x < COUT) sb[threadIdx.x] = skip_b[threadIdx.x];
    }
    __syncthreads();

    const int batch = blockIdx.y;
    in  += (long)batch * in_bstride;
    out += (long)batch * out_bstride;

    const int y = blockIdx.x;
    const int x = threadIdx.x;

    float acc[COUT];
#pragma unroll
    for (int c = 0; c < COUT; c++) acc[c] = bs[c];

    for (int ci = 0; ci < CIN; ci++) {
        const float* ip = in + ci * HW;
#pragma unroll
        for (int ky = 0; ky < 3; ky++) {
            int yy = y + ky - 1;
            bool rok = ((unsigned)yy < HGT);
            const float* rp = ip + yy * WID;
#pragma unroll
            for (int kx = 0; kx < 3; kx++) {
                int xx = x + kx - 1;
                float v = (rok && (unsigned)xx < WID) ? __ldg(rp + xx) : 0.f;
                const float* wp = ws + (ci * 9 + ky * 3 + kx) * COUT;
#pragma unroll
                for (int c4 = 0; c4 < COUT / 4; c4++) {
                    float4 wv = *(const float4*)(wp + 4 * c4);
                    acc[4 * c4 + 0] = fmaf(v, wv.x, acc[4 * c4 + 0]);
                    acc[4 * c4 + 1] = fmaf(v, wv.y, acc[4 * c4 + 1]);
                    acc[4 * c4 + 2] = fmaf(v, wv.z, acc[4 * c4 + 2]);
                    acc[4 * c4 + 3] = fmaf(v, wv.w, acc[4 * c4 + 3]);
                }
            }
        }
    }

    const int o = y * WID + x;
    if (SKIP) {
        const float* xp = skip_in + (long)batch * skip_bstride + o;
        float x0 = xp[0], x1 = xp[HW], x2 = xp[2 * HW];
#pragma unroll
        for (int c = 0; c < COUT; c++) {
            float r = RELU ? fmaxf(acc[c], 0.f) : acc[c];
            r += sb[c];
            r = fmaf(x0, sw[c], r);
            r = fmaf(x1, sw[COUT + c], r);
            r = fmaf(x2, sw[2 * COUT + c], r);
            out[c * HW + o] = r;
        }
    } else {
#pragma unroll
        for (int c = 0; c < COUT; c++)
            out[c * HW + o] = RELU ? fmaxf(acc[c], 0.f) : acc[c];
    }
}

// ---------------------------------------------------------------------------
// Fused 1x1 convs: K = kw*a, V = vw*a, Q = qw*b. One thread per pixel.
// ---------------------------------------------------------------------------
__global__ void __launch_bounds__(256) qkv_kernel(
    const float* __restrict__ a, const float* __restrict__ b,
    const float* __restrict__ qw, const float* __restrict__ qb,
    const float* __restrict__ kw, const float* __restrict__ kb,
    const float* __restrict__ vw, const float* __restrict__ vb,
    float* __restrict__ Q, float* __restrict__ K, float* __restrict__ V)
{
    __shared__ float s_qw[576], s_kw[576], s_vw[576];
    __shared__ float s_qb[24], s_kb[24], s_vb[24];
    for (int i = threadIdx.x; i < 576; i += 256) {
        int co = i % 24, ci = i / 24;
        s_qw[i] = qw[co * 24 + ci];
        s_kw[i] = kw[co * 24 + ci];
        s_vw[i] = vw[co * 24 + ci];
    }
    if (threadIdx.x < 24) {
        s_qb[threadIdx.x] = qb[threadIdx.x];
        s_kb[threadIdx.x] = kb[threadIdx.x];
        s_vb[threadIdx.x] = vb[threadIdx.x];
    }
    __syncthreads();

    const int idx = blockIdx.x * 256 + threadIdx.x;

    float iv[24];
#pragma unroll
    for (int c = 0; c < 24; c++) iv[c] = a[c * HW + idx];

    float acc[24];
#pragma unroll
    for (int c = 0; c < 24; c++) acc[c] = s_kb[c];
#pragma unroll
    for (int ci = 0; ci < 24; ci++) {
        float v = iv[ci];
        const float* wp = s_kw + ci * 24;
#pragma unroll
        for (int c = 0; c < 24; c++) acc[c] = fmaf(v, wp[c], acc[c]);
    }
#pragma unroll
    for (int c = 0; c < 24; c++) K[c * HW + idx] = acc[c];

#pragma unroll
    for (int c = 0; c < 24; c++) acc[c] = s_vb[c];
#pragma unroll
    for (int ci = 0; ci < 24; ci++) {
        float v = iv[ci];
        const float* wp = s_vw + ci * 24;
#pragma unroll
        for (int c = 0; c < 24; c++) acc[c] = fmaf(v, wp[c], acc[c]);
    }
#pragma unroll
    for (int c = 0; c < 24; c++) V[c * HW + idx] = acc[c];

#pragma unroll
    for (int c = 0; c < 24; c++) iv[c] = b[c * HW + idx];
#pragma unroll
    for (int c = 0; c < 24; c++) acc[c] = s_qb[c];
#pragma unroll
    for (int ci = 0; ci < 24; ci++) {
        float v = iv[ci];
        const float* wp = s_qw + ci * 24;
#pragma unroll
        for (int c = 0; c < 24; c++) acc[c] = fmaf(v, wp[c], acc[c]);
    }
#pragma unroll
    for (int c = 0; c < 24; c++) Q[c * HW + idx] = acc[c];
}

// ---------------------------------------------------------------------------
// Local 7x7 attention (pad 3, zero-padded unfold => OOB score = 0, included
// in softmax; OOB V = 0). out[0:24] = y + a, out[24:48] = b.
// ---------------------------------------------------------------------------
__global__ void __launch_bounds__(256) attn_kernel(
    const float* __restrict__ Q, const float* __restrict__ K,
    const float* __restrict__ Vv, const float* __restrict__ a,
    const float* __restrict__ b, float* __restrict__ out)
{
    const int idx = blockIdx.x * 256 + threadIdx.x;
    const int y = idx >> 8;
    const int x = idx & 255;

    float q[24];
#pragma unroll
    for (int c = 0; c < 24; c++) q[c] = Q[c * HW + idx];

    const float scale = 0.20412414523193154f;  // 1/sqrt(24)
    float s[49];
#pragma unroll
    for (int p = 0; p < 49; p++) {
        const int ny = y + p / 7 - 3;
        const int nx = x + p % 7 - 3;
        float d = 0.f;
        if ((unsigned)ny < HGT && (unsigned)nx < WID) {
            const float* kp = K + ny * WID + nx;
#pragma unroll
            for (int c = 0; c < 24; c++) d = fmaf(q[c], __ldg(kp + c * HW), d);
        }
        s[p] = d * scale;
    }

    float m = s[0];
#pragma unroll
    for (int p = 1; p < 49; p++) m = fmaxf(m, s[p]);
    float sum = 0.f;
#pragma unroll
    for (int p = 0; p < 49; p++) {
        s[p] = __expf(s[p] - m);
        sum += s[p];
    }
    const float inv = 1.0f / sum;

    float acc[24];
#pragma unroll
    for (int c = 0; c < 24; c++) acc[c] = 0.f;
#pragma unroll
    for (int p = 0; p < 49; p++) {
        const int ny = y + p / 7 - 3;
        const int nx = x + p % 7 - 3;
        if ((unsigned)ny < HGT && (unsigned)nx < WID) {
            const float wgt = s[p] * inv;
            const float* vp = Vv + ny * WID + nx;
#pragma unroll
            for (int c = 0; c < 24; c++) acc[c] = fmaf(wgt, __ldg(vp + c * HW), acc[c]);
        }
    }

#pragma unroll
    for (int c = 0; c < 24; c++) out[c * HW + idx] = acc[c] + a[c * HW + idx];
#pragma unroll
    for (int c = 0; c < 24; c++) out[(24 + c) * HW + idx] = b[c * HW + idx];
}

// ---------------------------------------------------------------------------
extern "C" void kernel_launch(void* const* d_in, const int* in_sizes, int n_in,
                              void* d_out, int out_size)
{
    const float* x      = (const float*)d_in[0];
    const float* w0     = (const float*)d_in[1];
    const float* b0     = (const float*)d_in[2];
    const float* w1     = (const float*)d_in[3];
    const float* b1     = (const float*)d_in[4];
    const float* w2     = (const float*)d_in[5];
    const float* b2     = (const float*)d_in[6];
    const float* w3     = (const float*)d_in[7];
    const float* b3     = (const float*)d_in[8];
    const float* skip_w = (const float*)d_in[9];
    const float* skip_b = (const float*)d_in[10];
    const float* q_w    = (const float*)d_in[11];
    const float* q_b    = (const float*)d_in[12];
    const float* k_w    = (const float*)d_in[13];
    const float* k_b    = (const float*)d_in[14];
    const float* v_w    = (const float*)d_in[15];
    const float* v_b    = (const float*)d_in[16];
    float* out = (float*)d_out;

    float *h0, *h1, *ab, *Qp, *Kp, *Vp;
    cudaGetSymbolAddress((void**)&h0, g_h0);
    cudaGetSymbolAddress((void**)&h1, g_h1);
    cudaGetSymbolAddress((void**)&ab, g_ab);
    cudaGetSymbolAddress((void**)&Qp, g_Q);
    cudaGetSymbolAddress((void**)&Kp, g_K);
    cudaGetSymbolAddress((void**)&Vp, g_V);

    const size_t sm48 = (size_t)(48 * 9 * 48 + 48) * sizeof(float);
    cudaFuncSetAttribute((const void*)conv3x3_kernel<48, 48, true, false>,
                         cudaFuncAttributeMaxDynamicSharedMemorySize, (int)sm48);

    dim3 g(HGT, 2);
    const size_t sm0 = (size_t)(3 * 9 * 48 + 48) * sizeof(float);
    const size_t sm3 = (size_t)(48 * 9 * 24 + 24 + 3 * 24 + 24) * sizeof(float);

    // conv0: x(3ch) -> h0(48ch), relu
    conv3x3_kernel<3, 48, true, false><<<g, 256, sm0>>>(
        x, w0, b0, h0, 3L * HW, 48L * HW, nullptr, 0, nullptr, nullptr);
    // conv1: h0 -> h1
    conv3x3_kernel<48, 48, true, false><<<g, 256, sm48>>>(
        h0, w1, b1, h1, 48L * HW, 48L * HW, nullptr, 0, nullptr, nullptr);
    // conv2: h1 -> h0
    conv3x3_kernel<48, 48, true, false><<<g, 256, sm48>>>(
        h1, w2, b2, h0, 48L * HW, 48L * HW, nullptr, 0, nullptr, nullptr);
    // conv3 + 1x1 skip: h0 -> ab (a = batch0, b = batch1)
    conv3x3_kernel<48, 24, true, true><<<g, 256, sm3>>>(
        h0, w3, b3, ab, 48L * HW, 24L * HW, x, 3L * HW, skip_w, skip_b);
    // Q/K/V 1x1 convs
    qkv_kernel<<<HW / 256, 256>>>(ab, ab + 24L * HW, q_w, q_b, k_w, k_b,
                                  v_w, v_b, Qp, Kp, Vp);
    // attention + residual + concat
    attn_kernel<<<HW / 256, 256>>>(Qp, Kp, Vp, ab, ab + 24L * HW, out);
}

// round 5
// speedup vs baseline: 1.5483x; 1.5483x over previous
#include <cuda_runtime.h>
#include <math.h>

#define HW 65536
#define WID 256
#define HGT 256

// Scratch (no allocations allowed)
__device__ float g_h0[2 * 48 * HW];
__device__ float g_h1[2 * 48 * HW];
__device__ float g_ab[2 * 24 * HW];   // batch0 = a, batch1 = b
__device__ float g_Q[24 * HW];
__device__ float g_K[24 * HW];
__device__ float g_V[24 * HW];

// ---------------------------------------------------------------------------
// Register-tiled direct 3x3 conv, NCHW, pad=1.
// Each thread: 4 vertical pixels x 12 output channels (outer product in regs).
// blockIdx.x = row strip (4 rows), blockIdx.y = cout group of 12,
// blockIdx.z = batch. block = 256 threads = 256 columns.
// Weights for this cgroup staged in smem transposed to [cin*9][12] so the
// inner loop is 3 broadcast LDS.128 per tap, reused across 4 pixels.
// ---------------------------------------------------------------------------
template <int CIN, int COUT, bool RELU, bool SKIP>
__global__ void __launch_bounds__(256, 2) conv3x3_tiled(
    const float* __restrict__ in, const float* __restrict__ w,
    const float* __restrict__ bias, float* __restrict__ out,
    long in_bstride, long out_bstride,
    const float* __restrict__ skip_in,
    const float* __restrict__ skip_w, const float* __restrict__ skip_b)
{
    extern __shared__ float smem[];
    float* ws = smem;                 // [CIN*9][12]
    float* bs = ws + CIN * 9 * 12;    // [12]
    float* sw = bs + 12;              // [3][12] skip weights (transposed)
    float* sb = sw + (SKIP ? 36 : 0); // [12]

    const int cg = blockIdx.y;        // cout group
    const int tid = threadIdx.x;

    for (int i = tid; i < CIN * 9 * 12; i += 256) {
        int cl = i % 12;
        int r  = i / 12;
        int ci = r / 9;
        int k  = r % 9;
        ws[i] = w[((cg * 12 + cl) * CIN + ci) * 9 + k];
    }
    if (tid < 12) bs[tid] = bias[cg * 12 + tid];
    if (SKIP) {
        if (tid < 36) {
            int cl = tid % 12, ci = tid / 12;
            sw[tid] = skip_w[(cg * 12 + cl) * 3 + ci];
        }
        if (tid >= 64 && tid < 76) sb[tid - 64] = skip_b[cg * 12 + tid - 64];
    }
    __syncthreads();

    const int batch = blockIdx.z;
    in  += (long)batch * in_bstride;
    out += (long)batch * out_bstride;

    const int x  = tid;
    const int y0 = blockIdx.x * 4;
    const bool xlo = (x != 0);
    const bool xhi = (x != WID - 1);

    float acc[4][12];
#pragma unroll
    for (int p = 0; p < 4; p++)
#pragma unroll
        for (int c = 0; c < 12; c++) acc[p][c] = bs[c];

    for (int ci = 0; ci < CIN; ci++) {
        const float* ip = in + (long)ci * HW;

        // Load the 6x3 input window for this thread's 4-pixel column.
        float iv[6][3];
#pragma unroll
        for (int r = 0; r < 6; r++) {
            int yy = y0 + r - 1;
            bool rok = ((unsigned)yy < HGT);
            const float* rp = ip + yy * WID + x;
            iv[r][0] = (rok && xlo) ? __ldg(rp - 1) : 0.f;
            iv[r][1] = rok ? __ldg(rp) : 0.f;
            iv[r][2] = (rok && xhi) ? __ldg(rp + 1) : 0.f;
        }

#pragma unroll
        for (int t = 0; t < 9; t++) {
            const int ky = t / 3;
            const int kx = t % 3;
            const float4* wp = (const float4*)(ws + (ci * 9 + t) * 12);
            float4 w0 = wp[0], w1 = wp[1], w2 = wp[2];
#pragma unroll
            for (int p = 0; p < 4; p++) {
                float v = iv[p + ky][kx];
                acc[p][0]  = fmaf(v, w0.x, acc[p][0]);
                acc[p][1]  = fmaf(v, w0.y, acc[p][1]);
                acc[p][2]  = fmaf(v, w0.z, acc[p][2]);
                acc[p][3]  = fmaf(v, w0.w, acc[p][3]);
                acc[p][4]  = fmaf(v, w1.x, acc[p][4]);
                acc[p][5]  = fmaf(v, w1.y, acc[p][5]);
                acc[p][6]  = fmaf(v, w1.z, acc[p][6]);
                acc[p][7]  = fmaf(v, w1.w, acc[p][7]);
                acc[p][8]  = fmaf(v, w2.x, acc[p][8]);
                acc[p][9]  = fmaf(v, w2.y, acc[p][9]);
                acc[p][10] = fmaf(v, w2.z, acc[p][10]);
                acc[p][11] = fmaf(v, w2.w, acc[p][11]);
            }
        }
    }

#pragma unroll
    for (int p = 0; p < 4; p++) {
        const int o = (y0 + p) * WID + x;
        if (SKIP) {
            const float* xp = skip_in + (long)batch * 3 * HW + o;
            float x0 = xp[0], x1 = xp[HW], x2 = xp[2 * HW];
#pragma unroll
            for (int c = 0; c < 12; c++) {
                float r = RELU ? fmaxf(acc[p][c], 0.f) : acc[p][c];
                r += sb[c];
                r = fmaf(x0, sw[c], r);
                r = fmaf(x1, sw[12 + c], r);
                r = fmaf(x2, sw[24 + c], r);
                out[(long)(cg * 12 + c) * HW + o] = r;
            }
        } else {
#pragma unroll
            for (int c = 0; c < 12; c++)
                out[(long)(cg * 12 + c) * HW + o] =
                    RELU ? fmaxf(acc[p][c], 0.f) : acc[p][c];
        }
    }
}

// ---------------------------------------------------------------------------
// Fused 1x1 convs: K = kw*a, V = vw*a, Q = qw*b. One thread per pixel.
// ---------------------------------------------------------------------------
__global__ void __launch_bounds__(256) qkv_kernel(
    const float* __restrict__ a, const float* __restrict__ b,
    const float* __restrict__ qw, const float* __restrict__ qb,
    const float* __restrict__ kw, const float* __restrict__ kb,
    const float* __restrict__ vw, const float* __restrict__ vb,
    float* __restrict__ Q, float* __restrict__ K, float* __restrict__ V)
{
    __shared__ float s_qw[576], s_kw[576], s_vw[576];
    __shared__ float s_qb[24], s_kb[24], s_vb[24];
    for (int i = threadIdx.x; i < 576; i += 256) {
        int co = i % 24, ci = i / 24;
        s_qw[i] = qw[co * 24 + ci];
        s_kw[i] = kw[co * 24 + ci];
        s_vw[i] = vw[co * 24 + ci];
    }
    if (threadIdx.x < 24) {
        s_qb[threadIdx.x] = qb[threadIdx.x];
        s_kb[threadIdx.x] = kb[threadIdx.x];
        s_vb[threadIdx.x] = vb[threadIdx.x];
    }
    __syncthreads();

    const int idx = blockIdx.x * 256 + threadIdx.x;

    float iv[24];
#pragma unroll
    for (int c = 0; c < 24; c++) iv[c] = a[c * HW + idx];

    float acc[24];
#pragma unroll
    for (int c = 0; c < 24; c++) acc[c] = s_kb[c];
#pragma unroll
    for (int ci = 0; ci < 24; ci++) {
        float v = iv[ci];
        const float* wp = s_kw + ci * 24;
#pragma unroll
        for (int c = 0; c < 24; c++) acc[c] = fmaf(v, wp[c], acc[c]);
    }
#pragma unroll
    for (int c = 0; c < 24; c++) K[c * HW + idx] = acc[c];

#pragma unroll
    for (int c = 0; c < 24; c++) acc[c] = s_vb[c];
#pragma unroll
    for (int ci = 0; ci < 24; ci++) {
        float v = iv[ci];
        const float* wp = s_vw + ci * 24;
#pragma unroll
        for (int c = 0; c < 24; c++) acc[c] = fmaf(v, wp[c], acc[c]);
    }
#pragma unroll
    for (int c = 0; c < 24; c++) V[c * HW + idx] = acc[c];

#pragma unroll
    for (int c = 0; c < 24; c++) iv[c] = b[c * HW + idx];
#pragma unroll
    for (int c = 0; c < 24; c++) acc[c] = s_qb[c];
#pragma unroll
    for (int ci = 0; ci < 24; ci++) {
        float v = iv[ci];
        const float* wp = s_qw + ci * 24;
#pragma unroll
        for (int c = 0; c < 24; c++) acc[c] = fmaf(v, wp[c], acc[c]);
    }
#pragma unroll
    for (int c = 0; c < 24; c++) Q[c * HW + idx] = acc[c];
}

// ---------------------------------------------------------------------------
// Local 7x7 attention (pad 3, zero-padded unfold => OOB score = 0, included
// in softmax; OOB V = 0). out[0:24] = y + a, out[24:48] = b.
// ---------------------------------------------------------------------------
__global__ void __launch_bounds__(256) attn_kernel(
    const float* __restrict__ Q, const float* __restrict__ K,
    const float* __restrict__ Vv, const float* __restrict__ a,
    const float* __restrict__ b, float* __restrict__ out)
{
    const int idx = blockIdx.x * 256 + threadIdx.x;
    const int y = idx >> 8;
    const int x = idx & 255;

    float q[24];
#pragma unroll
    for (int c = 0; c < 24; c++) q[c] = Q[c * HW + idx];

    const float scale = 0.20412414523193154f;  // 1/sqrt(24)
    float s[49];
#pragma unroll
    for (int p = 0; p < 49; p++) {
        const int ny = y + p / 7 - 3;
        const int nx = x + p % 7 - 3;
        float d = 0.f;
        if ((unsigned)ny < HGT && (unsigned)nx < WID) {
            const float* kp = K + ny * WID + nx;
#pragma unroll
            for (int c = 0; c < 24; c++) d = fmaf(q[c], __ldg(kp + c * HW), d);
        }
        s[p] = d * scale;
    }

    float m = s[0];
#pragma unroll
    for (int p = 1; p < 49; p++) m = fmaxf(m, s[p]);
    float sum = 0.f;
#pragma unroll
    for (int p = 0; p < 49; p++) {
        s[p] = __expf(s[p] - m);
        sum += s[p];
    }
    const float inv = 1.0f / sum;

    float acc[24];
#pragma unroll
    for (int c = 0; c < 24; c++) acc[c] = 0.f;
#pragma unroll
    for (int p = 0; p < 49; p++) {
        const int ny = y + p / 7 - 3;
        const int nx = x + p % 7 - 3;
        if ((unsigned)ny < HGT && (unsigned)nx < WID) {
            const float wgt = s[p] * inv;
            const float* vp = Vv + ny * WID + nx;
#pragma unroll
            for (int c = 0; c < 24; c++) acc[c] = fmaf(wgt, __ldg(vp + c * HW), acc[c]);
        }
    }

#pragma unroll
    for (int c = 0; c < 24; c++) out[c * HW + idx] = acc[c] + a[c * HW + idx];
#pragma unroll
    for (int c = 0; c < 24; c++) out[(24 + c) * HW + idx] = b[c * HW + idx];
}

// ---------------------------------------------------------------------------
extern "C" void kernel_launch(void* const* d_in, const int* in_sizes, int n_in,
                              void* d_out, int out_size)
{
    const float* x      = (const float*)d_in[0];
    const float* w0     = (const float*)d_in[1];
    const float* b0     = (const float*)d_in[2];
    const float* w1     = (const float*)d_in[3];
    const float* b1     = (const float*)d_in[4];
    const float* w2     = (const float*)d_in[5];
    const float* b2     = (const float*)d_in[6];
    const float* w3     = (const float*)d_in[7];
    const float* b3     = (const float*)d_in[8];
    const float* skip_w = (const float*)d_in[9];
    const float* skip_b = (const float*)d_in[10];
    const float* q_w    = (const float*)d_in[11];
    const float* q_b    = (const float*)d_in[12];
    const float* k_w    = (const float*)d_in[13];
    const float* k_b    = (const float*)d_in[14];
    const float* v_w    = (const float*)d_in[15];
    const float* v_b    = (const float*)d_in[16];
    float* out = (float*)d_out;

    float *h0, *h1, *ab, *Qp, *Kp, *Vp;
    cudaGetSymbolAddress((void**)&h0, g_h0);
    cudaGetSymbolAddress((void**)&h1, g_h1);
    cudaGetSymbolAddress((void**)&ab, g_ab);
    cudaGetSymbolAddress((void**)&Qp, g_Q);
    cudaGetSymbolAddress((void**)&Kp, g_K);
    cudaGetSymbolAddress((void**)&Vp, g_V);

    const size_t sm0  = (size_t)(3 * 9 * 12 + 12) * sizeof(float);
    const size_t sm48 = (size_t)(48 * 9 * 12 + 12) * sizeof(float);
    const size_t sm3  = (size_t)(48 * 9 * 12 + 12 + 36 + 12) * sizeof(float);

    // conv0: x(3ch) -> h0(48ch), relu.  grid: 64 strips x 4 cgroups x 2 batches
    conv3x3_tiled<3, 48, true, false><<<dim3(64, 4, 2), 256, sm0>>>(
        x, w0, b0, h0, 3L * HW, 48L * HW, nullptr, nullptr, nullptr);
    // conv1: h0 -> h1
    conv3x3_tiled<48, 48, true, false><<<dim3(64, 4, 2), 256, sm48>>>(
        h0, w1, b1, h1, 48L * HW, 48L * HW, nullptr, nullptr, nullptr);
    // conv2: h1 -> h0
    conv3x3_tiled<48, 48, true, false><<<dim3(64, 4, 2), 256, sm48>>>(
        h1, w2, b2, h0, 48L * HW, 48L * HW, nullptr, nullptr, nullptr);
    // conv3 + 1x1 skip: h0 -> ab (a = batch0, b = batch1)
    conv3x3_tiled<48, 24, true, true><<<dim3(64, 2, 2), 256, sm3>>>(
        h0, w3, b3, ab, 48L * HW, 24L * HW, x, skip_w, skip_b);
    // Q/K/V 1x1 convs
    qkv_kernel<<<HW / 256, 256>>>(ab, ab + 24L * HW, q_w, q_b, k_w, k_b,
                                  v_w, v_b, Qp, Kp, Vp);
    // attention + residual + concat
    attn_kernel<<<HW / 256, 256>>>(Qp, Kp, Vp, ab, ab + 24L * HW, out);
}

// round 6
// speedup vs baseline: 1.7245x; 1.1138x over previous
#include <cuda_runtime.h>
#include <math.h>

#define HW 65536
#define WID 256
#define HGT 256

// Scratch (no allocations allowed)
__device__ float g_h0[2 * 48 * HW];
__device__ float g_h1[2 * 48 * HW];
__device__ float g_ab[2 * 24 * HW];   // batch0 = a, batch1 = b
__device__ float g_Q[24 * HW];
__device__ float g_K[24 * HW];
__device__ float g_V[24 * HW];

// ---- packed f32x2 helpers (sm_103a FFMA2 path, PTX-only) --------------------
__device__ __forceinline__ unsigned long long ffma2(
    unsigned long long a, unsigned long long b, unsigned long long c)
{
    unsigned long long d;
    asm("fma.rn.f32x2 %0, %1, %2, %3;" : "=l"(d) : "l"(a), "l"(b), "l"(c));
    return d;
}
__device__ __forceinline__ unsigned long long pack2(float v)
{
    unsigned long long d;
    asm("mov.b64 %0, {%1, %1};" : "=l"(d) : "r"(__float_as_uint(v)));
    return d;
}
__device__ __forceinline__ unsigned long long pack2v(float lo, float hi)
{
    unsigned long long d;
    asm("mov.b64 %0, {%1, %2};" : "=l"(d) : "r"(__float_as_uint(lo)), "r"(__float_as_uint(hi)));
    return d;
}
__device__ __forceinline__ void unpack2(unsigned long long v, float& lo, float& hi)
{
    unsigned ulo, uhi;
    asm("mov.b64 {%0, %1}, %2;" : "=r"(ulo), "=r"(uhi) : "l"(v));
    lo = __uint_as_float(ulo);
    hi = __uint_as_float(uhi);
}

// ---------------------------------------------------------------------------
// Register-tiled direct 3x3 conv, NCHW, pad=1, packed f32x2 accumulators.
// Each thread: 4 vertical pixels x 12 output channels (= 6 f32x2 lanes).
// blockIdx.x = row strip (4 rows), blockIdx.y = cout group of 12,
// blockIdx.z = batch. block = 256 threads = 256 columns.
// Weights staged in smem transposed to [cin*9][12]; inner loop reads them as
// ulonglong2 (LDS.128) and issues 6 FFMA2 per pixel per tap.
// ---------------------------------------------------------------------------
template <int CIN, int COUT, bool RELU, bool SKIP>
__global__ void __launch_bounds__(256, 2) conv3x3_tiled(
    const float* __restrict__ in, const float* __restrict__ w,
    const float* __restrict__ bias, float* __restrict__ out,
    long in_bstride, long out_bstride,
    const float* __restrict__ skip_in,
    const float* __restrict__ skip_w, const float* __restrict__ skip_b)
{
    extern __shared__ float smem[];
    float* ws = smem;                 // [CIN*9][12]
    float* bs = ws + CIN * 9 * 12;    // [12]
    float* sw = bs + 12;              // [3][12] skip weights (transposed)
    float* sb = sw + (SKIP ? 36 : 0); // [12]

    const int cg = blockIdx.y;        // cout group
    const int tid = threadIdx.x;

    for (int i = tid; i < CIN * 9 * 12; i += 256) {
        int cl = i % 12;
        int r  = i / 12;
        int ci = r / 9;
        int k  = r % 9;
        ws[i] = w[((cg * 12 + cl) * CIN + ci) * 9 + k];
    }
    if (tid < 12) bs[tid] = bias[cg * 12 + tid];
    if (SKIP) {
        if (tid < 36) {
            int cl = tid % 12, ci = tid / 12;
            sw[tid] = skip_w[(cg * 12 + cl) * 3 + ci];
        }
        if (tid >= 64 && tid < 76) sb[tid - 64] = skip_b[cg * 12 + tid - 64];
    }
    __syncthreads();

    const int batch = blockIdx.z;
    in  += (long)batch * in_bstride;
    out += (long)batch * out_bstride;

    const int x  = tid;
    const int y0 = blockIdx.x * 4;
    const bool xlo = (x != 0);
    const bool xhi = (x != WID - 1);

    // acc[p][j] packs output channels (2j, 2j+1) for pixel p
    unsigned long long acc[4][6];
#pragma unroll
    for (int j = 0; j < 6; j++) {
        unsigned long long b2 = pack2v(bs[2 * j], bs[2 * j + 1]);
#pragma unroll
        for (int p = 0; p < 4; p++) acc[p][j] = b2;
    }

    for (int ci = 0; ci < CIN; ci++) {
        const float* ip = in + (long)ci * HW;

        // Load the 6x3 input window for this thread's 4-pixel column.
        float iv[6][3];
#pragma unroll
        for (int r = 0; r < 6; r++) {
            int yy = y0 + r - 1;
            bool rok = ((unsigned)yy < HGT);
            const float* rp = ip + yy * WID + x;
            iv[r][0] = (rok && xlo) ? __ldg(rp - 1) : 0.f;
            iv[r][1] = rok ? __ldg(rp) : 0.f;
            iv[r][2] = (rok && xhi) ? __ldg(rp + 1) : 0.f;
        }

#pragma unroll
        for (int t = 0; t < 9; t++) {
            const int ky = t / 3;
            const int kx = t % 3;
            const ulonglong2* wp = (const ulonglong2*)(ws + (ci * 9 + t) * 12);
            ulonglong2 wa = wp[0];   // ch 0-3
            ulonglong2 wb = wp[1];   // ch 4-7
            ulonglong2 wc = wp[2];   // ch 8-11
#pragma unroll
            for (int p = 0; p < 4; p++) {
                unsigned long long vv = pack2(iv[p + ky][kx]);
                acc[p][0] = ffma2(vv, wa.x, acc[p][0]);
                acc[p][1] = ffma2(vv, wa.y, acc[p][1]);
                acc[p][2] = ffma2(vv, wb.x, acc[p][2]);
                acc[p][3] = ffma2(vv, wb.y, acc[p][3]);
                acc[p][4] = ffma2(vv, wc.x, acc[p][4]);
                acc[p][5] = ffma2(vv, wc.y, acc[p][5]);
            }
        }
    }

#pragma unroll
    for (int p = 0; p < 4; p++) {
        const int o = (y0 + p) * WID + x;
        float av[12];
#pragma unroll
        for (int j = 0; j < 6; j++) unpack2(acc[p][j], av[2 * j], av[2 * j + 1]);

        if (SKIP) {
            const float* xp = skip_in + (long)batch * 3 * HW + o;
            float x0 = xp[0], x1 = xp[HW], x2 = xp[2 * HW];
#pragma unroll
            for (int c = 0; c < 12; c++) {
                float r = RELU ? fmaxf(av[c], 0.f) : av[c];
                r += sb[c];
                r = fmaf(x0, sw[c], r);
                r = fmaf(x1, sw[12 + c], r);
                r = fmaf(x2, sw[24 + c], r);
                out[(long)(cg * 12 + c) * HW + o] = r;
            }
        } else {
#pragma unroll
            for (int c = 0; c < 12; c++)
                out[(long)(cg * 12 + c) * HW + o] =
                    RELU ? fmaxf(av[c], 0.f) : av[c];
        }
    }
}

// ---------------------------------------------------------------------------
// Fused 1x1 convs: K = kw*a, V = vw*a, Q = qw*b. One thread per pixel.
// ---------------------------------------------------------------------------
__global__ void __launch_bounds__(256) qkv_kernel(
    const float* __restrict__ a, const float* __restrict__ b,
    const float* __restrict__ qw, const float* __restrict__ qb,
    const float* __restrict__ kw, const float* __restrict__ kb,
    const float* __restrict__ vw, const float* __restrict__ vb,
    float* __restrict__ Q, float* __restrict__ K, float* __restrict__ V)
{
    __shared__ float s_qw[576], s_kw[576], s_vw[576];
    __shared__ float s_qb[24], s_kb[24], s_vb[24];
    for (int i = threadIdx.x; i < 576; i += 256) {
        int co = i % 24, ci = i / 24;
        s_qw[i] = qw[co * 24 + ci];
        s_kw[i] = kw[co * 24 + ci];
        s_vw[i] = vw[co * 24 + ci];
    }
    if (threadIdx.x < 24) {
        s_qb[threadIdx.x] = qb[threadIdx.x];
        s_kb[threadIdx.x] = kb[threadIdx.x];
        s_vb[threadIdx.x] = vb[threadIdx.x];
    }
    __syncthreads();

    const int idx = blockIdx.x * 256 + threadIdx.x;

    float iv[24];
#pragma unroll
    for (int c = 0; c < 24; c++) iv[c] = a[c * HW + idx];

    float acc[24];
#pragma unroll
    for (int c = 0; c < 24; c++) acc[c] = s_kb[c];
#pragma unroll
    for (int ci = 0; ci < 24; ci++) {
        float v = iv[ci];
        const float* wp = s_kw + ci * 24;
#pragma unroll
        for (int c = 0; c < 24; c++) acc[c] = fmaf(v, wp[c], acc[c]);
    }
#pragma unroll
    for (int c = 0; c < 24; c++) K[c * HW + idx] = acc[c];

#pragma unroll
    for (int c = 0; c < 24; c++) acc[c] = s_vb[c];
#pragma unroll
    for (int ci = 0; ci < 24; ci++) {
        float v = iv[ci];
        const float* wp = s_vw + ci * 24;
#pragma unroll
        for (int c = 0; c < 24; c++) acc[c] = fmaf(v, wp[c], acc[c]);
    }
#pragma unroll
    for (int c = 0; c < 24; c++) V[c * HW + idx] = acc[c];

#pragma unroll
    for (int c = 0; c < 24; c++) iv[c] = b[c * HW + idx];
#pragma unroll
    for (int c = 0; c < 24; c++) acc[c] = s_qb[c];
#pragma unroll
    for (int ci = 0; ci < 24; ci++) {
        float v = iv[ci];
        const float* wp = s_qw + ci * 24;
#pragma unroll
        for (int c = 0; c < 24; c++) acc[c] = fmaf(v, wp[c], acc[c]);
    }
#pragma unroll
    for (int c = 0; c < 24; c++) Q[c * HW + idx] = acc[c];
}

// ---------------------------------------------------------------------------
// Local 7x7 attention (pad 3, zero-padded unfold => OOB score = 0, included
// in softmax; OOB V = 0). out[0:24] = y + a, out[24:48] = b.
// ---------------------------------------------------------------------------
__global__ void __launch_bounds__(256) attn_kernel(
    const float* __restrict__ Q, const float* __restrict__ K,
    const float* __restrict__ Vv, const float* __restrict__ a,
    const float* __restrict__ b, float* __restrict__ out)
{
    const int idx = blockIdx.x * 256 + threadIdx.x;
    const int y = idx >> 8;
    const int x = idx & 255;

    float q[24];
#pragma unroll
    for (int c = 0; c < 24; c++) q[c] = Q[c * HW + idx];

    const float scale = 0.20412414523193154f;  // 1/sqrt(24)
    float s[49];
#pragma unroll
    for (int p = 0; p < 49; p++) {
        const int ny = y + p / 7 - 3;
        const int nx = x + p % 7 - 3;
        float d = 0.f;
        if ((unsigned)ny < HGT && (unsigned)nx < WID) {
            const float* kp = K + ny * WID + nx;
#pragma unroll
            for (int c = 0; c < 24; c++) d = fmaf(q[c], __ldg(kp + c * HW), d);
        }
        s[p] = d * scale;
    }

    float m = s[0];
#pragma unroll
    for (int p = 1; p < 49; p++) m = fmaxf(m, s[p]);
    float sum = 0.f;
#pragma unroll
    for (int p = 0; p < 49; p++) {
        s[p] = __expf(s[p] - m);
        sum += s[p];
    }
    const float inv = 1.0f / sum;

    float acc[24];
#pragma unroll
    for (int c = 0; c < 24; c++) acc[c] = 0.f;
#pragma unroll
    for (int p = 0; p < 49; p++) {
        const int ny = y + p / 7 - 3;
        const int nx = x + p % 7 - 3;
        if ((unsigned)ny < HGT && (unsigned)nx < WID) {
            const float wgt = s[p] * inv;
            const float* vp = Vv + ny * WID + nx;
#pragma unroll
            for (int c = 0; c < 24; c++) acc[c] = fmaf(wgt, __ldg(vp + c * HW), acc[c]);
        }
    }

#pragma unroll
    for (int c = 0; c < 24; c++) out[c * HW + idx] = acc[c] + a[c * HW + idx];
#pragma unroll
    for (int c = 0; c < 24; c++) out[(24 + c) * HW + idx] = b[c * HW + idx];
}

// ---------------------------------------------------------------------------
extern "C" void kernel_launch(void* const* d_in, const int* in_sizes, int n_in,
                              void* d_out, int out_size)
{
    const float* x      = (const float*)d_in[0];
    const float* w0     = (const float*)d_in[1];
    const float* b0     = (const float*)d_in[2];
    const float* w1     = (const float*)d_in[3];
    const float* b1     = (const float*)d_in[4];
    const float* w2     = (const float*)d_in[5];
    const float* b2     = (const float*)d_in[6];
    const float* w3     = (const float*)d_in[7];
    const float* b3     = (const float*)d_in[8];
    const float* skip_w = (const float*)d_in[9];
    const float* skip_b = (const float*)d_in[10];
    const float* q_w    = (const float*)d_in[11];
    const float* q_b    = (const float*)d_in[12];
    const float* k_w    = (const float*)d_in[13];
    const float* k_b    = (const float*)d_in[14];
    const float* v_w    = (const float*)d_in[15];
    const float* v_b    = (const float*)d_in[16];
    float* out = (float*)d_out;

    float *h0, *h1, *ab, *Qp, *Kp, *Vp;
    cudaGetSymbolAddress((void**)&h0, g_h0);
    cudaGetSymbolAddress((void**)&h1, g_h1);
    cudaGetSymbolAddress((void**)&ab, g_ab);
    cudaGetSymbolAddress((void**)&Qp, g_Q);
    cudaGetSymbolAddress((void**)&Kp, g_K);
    cudaGetSymbolAddress((void**)&Vp, g_V);

    const size_t sm0  = (size_t)(3 * 9 * 12 + 12) * sizeof(float);
    const size_t sm48 = (size_t)(48 * 9 * 12 + 12) * sizeof(float);
    const size_t sm3  = (size_t)(48 * 9 * 12 + 12 + 36 + 12) * sizeof(float);

    // conv0: x(3ch) -> h0(48ch), relu.  grid: 64 strips x 4 cgroups x 2 batches
    conv3x3_tiled<3, 48, true, false><<<dim3(64, 4, 2), 256, sm0>>>(
        x, w0, b0, h0, 3L * HW, 48L * HW, nullptr, nullptr, nullptr);
    // conv1: h0 -> h1
    conv3x3_tiled<48, 48, true, false><<<dim3(64, 4, 2), 256, sm48>>>(
        h0, w1, b1, h1, 48L * HW, 48L * HW, nullptr, nullptr, nullptr);
    // conv2: h1 -> h0
    conv3x3_tiled<48, 48, true, false><<<dim3(64, 4, 2), 256, sm48>>>(
        h1, w2, b2, h0, 48L * HW, 48L * HW, nullptr, nullptr, nullptr);
    // conv3 + 1x1 skip: h0 -> ab (a = batch0, b = batch1)
    conv3x3_tiled<48, 24, true, true><<<dim3(64, 2, 2), 256, sm3>>>(
        h0, w3, b3, ab, 48L * HW, 24L * HW, x, skip_w, skip_b);
    // Q/K/V 1x1 convs
    qkv_kernel<<<HW / 256, 256>>>(ab, ab + 24L * HW, q_w, q_b, k_w, k_b,
                                  v_w, v_b, Qp, Kp, Vp);
    // attention + residual + concat
    attn_kernel<<<HW / 256, 256>>>(Qp, Kp, Vp, ab, ab + 24L * HW, out);
}

// round 7
// speedup vs baseline: 2.9920x; 1.7350x over previous
#include <cuda_runtime.h>
#include <math.h>

#define HW 65536
#define WID 256
#define HGT 256

// Scratch (no allocations allowed)
__device__ float g_h0[2 * 48 * HW];
__device__ float g_h1[2 * 48 * HW];
__device__ float g_ab[2 * 24 * HW];   // batch0 = a, batch1 = b
__device__ float g_Q[24 * HW];
__device__ float g_K[24 * HW];
__device__ float g_V[24 * HW];
__device__ unsigned g_warr[60000];    // fragment-arranged tf32 weights

// ---- tf32 helpers ----------------------------------------------------------
__device__ __forceinline__ unsigned f2tf32(float f) {
    unsigned r;
    asm("cvt.rna.tf32.f32 %0, %1;" : "=r"(r) : "f"(f));
    return r;
}
__device__ __forceinline__ void mma_tf32(float c[4], const unsigned* a,
                                         unsigned b0, unsigned b1) {
    asm("mma.sync.aligned.m16n8k8.row.col.f32.tf32.tf32.f32 "
        "{%0,%1,%2,%3}, {%4,%5,%6,%7}, {%8,%9}, {%0,%1,%2,%3};"
        : "+f"(c[0]), "+f"(c[1]), "+f"(c[2]), "+f"(c[3])
        : "r"(a[0]), "r"(a[1]), "r"(a[2]), "r"(a[3]), "r"(b0), "r"(b1));
}

// ---------------------------------------------------------------------------
// Pre-arrange conv weights into per-lane mma fragment order (tf32).
// Consumer reads: warr[(((tap*KSTEPS+s)*MF+mf)*32 + lane)*4 + j]
//   a0:(r,c) a1:(r+8,c) a2:(r,c+4) a3:(r+8,c+4); r=cout_local, c=ci_local.
// ---------------------------------------------------------------------------
template <int CIN, int COUT, int KSTEPS, int MF>
__global__ void arrange_w(const float* __restrict__ w, unsigned* __restrict__ dst)
{
    int idx = blockIdx.x * 256 + threadIdx.x;
    const int total = 9 * KSTEPS * MF * 128;
    if (idx >= total) return;
    int j    = idx & 3;
    int lane = (idx >> 2) & 31;
    int rest = idx >> 7;               // (tap*KSTEPS+s)*MF+mf
    int mf   = rest % MF;
    int ts   = rest / MF;
    int s    = ts % KSTEPS;
    int tap  = ts / KSTEPS;
    int cout = 16 * mf + (lane >> 2) + ((j & 1) << 3);
    int ci   = 8 * s + (lane & 3) + ((j & 2) << 1);
    float v = (cout < COUT && ci < CIN) ? w[(cout * CIN + ci) * 9 + tap] : 0.f;
    dst[idx] = f2tf32(v);
}

// ---------------------------------------------------------------------------
// Tensor-core 3x3 conv (implicit GEMM, tf32 mma.sync).
// CTA = 16x16 pixel tile, 256 threads (8 warps). Warp w: pixels [32w,32w+32),
// all COUT outputs. A = weights (fragment-order LDG.128 from g_warr),
// B = input pixels gathered per-lane from the staged smem tile (halo'd 18x18,
// ci-stride CIP for bank-conflict-free B loads). Taps are address shifts.
// grid = (16, 16, 2 batches).
// ---------------------------------------------------------------------------
template <int CIN, int CIN_STAGE, int COUT, int KSTEPS, int MF, int CIP, bool SKIP>
__global__ void __launch_bounds__(256, 2) conv_mma(
    const float* __restrict__ in, const unsigned* __restrict__ warr,
    const float* __restrict__ bias, float* __restrict__ out,
    long in_bs, long out_bs,
    const float* __restrict__ skip_in, const float* __restrict__ skip_w,
    const float* __restrict__ skip_b)
{
    extern __shared__ unsigned s_in[];   // [18*18][CIP] tf32
    const int tid = threadIdx.x;
    const int batch = blockIdx.z;
    in  += (long)batch * in_bs;
    out += (long)batch * out_bs;
    const int x0 = blockIdx.x * 16, y0 = blockIdx.y * 16;

    // Stage halo'd input tile, fp32 -> tf32(rna)
    for (int idx = tid; idx < 324 * CIN_STAGE; idx += 256) {
        int ci = idx / 324, rc = idx % 324;
        int r = rc / 18, c = rc % 18;
        int gy = y0 - 1 + r, gx = x0 - 1 + c;
        float v = 0.f;
        if (ci < CIN && (unsigned)gy < HGT && (unsigned)gx < WID)
            v = in[(long)ci * HW + gy * WID + gx];
        s_in[rc * CIP + ci] = f2tf32(v);
    }
    __syncthreads();

    const int w = tid >> 5, lane = tid & 31;
    const int q = lane >> 2, t4 = lane & 3;

    float acc[MF][4][4];
#pragma unroll
    for (int mf = 0; mf < MF; mf++)
#pragma unroll
        for (int nf = 0; nf < 4; nf++)
#pragma unroll
            for (int j = 0; j < 4; j++) acc[mf][nf][j] = 0.f;

    // per-nfrag base address: pixel (y_n, x_n), +1 halo origin, + ci lane%4
    int base[4];
#pragma unroll
    for (int nf = 0; nf < 4; nf++) {
        int yn = 2 * w + (nf >> 1);
        int xn = 8 * (nf & 1) + q;
        base[nf] = ((yn + 1) * 18 + (xn + 1)) * CIP + t4;
    }
    const uint4* wp = (const uint4*)warr + lane;

#pragma unroll
    for (int tap = 0; tap < 9; tap++) {
        const int dy = tap / 3 - 1, dx = tap % 3 - 1;
        const int off = (dy * 18 + dx) * CIP;
#pragma unroll
        for (int s = 0; s < KSTEPS; s++) {
            uint4 a[MF];
#pragma unroll
            for (int mf = 0; mf < MF; mf++)
                a[mf] = wp[((tap * KSTEPS + s) * MF + mf) * 32];
#pragma unroll
            for (int nf = 0; nf < 4; nf++) {
                int ad = base[nf] + off + 8 * s;
                unsigned b0 = s_in[ad];
                unsigned b1 = s_in[ad + 4];
#pragma unroll
                for (int mf = 0; mf < MF; mf++)
                    mma_tf32(acc[mf][nf], (const unsigned*)&a[mf], b0, b1);
            }
        }
    }

    // Epilogue: bias + relu (+1x1 skip), write fp32 NCHW.
#pragma unroll
    for (int mf = 0; mf < MF; mf++) {
        const int coutL = 16 * mf + q;
        const int coutH = coutL + 8;
        const float bL = (coutL < COUT) ? __ldg(bias + coutL) : 0.f;
        const float bH = (coutH < COUT) ? __ldg(bias + coutH) : 0.f;
#pragma unroll
        for (int nf = 0; nf < 4; nf++) {
            const int gy = y0 + 2 * w + (nf >> 1);
            const int gx = x0 + 8 * (nf & 1) + 2 * t4;
            const int o = gy * WID + gx;
            float v0 = fmaxf(acc[mf][nf][0] + bL, 0.f);
            float v1 = fmaxf(acc[mf][nf][1] + bL, 0.f);
            float v2 = fmaxf(acc[mf][nf][2] + bH, 0.f);
            float v3 = fmaxf(acc[mf][nf][3] + bH, 0.f);
            if (SKIP) {
                const float* xp = skip_in + (long)batch * 3 * HW;
                float xa0 = __ldg(xp + o),          xb0 = __ldg(xp + o + 1);
                float xa1 = __ldg(xp + HW + o),     xb1 = __ldg(xp + HW + o + 1);
                float xa2 = __ldg(xp + 2 * HW + o), xb2 = __ldg(xp + 2 * HW + o + 1);
                if (coutL < COUT) {
                    float sb = __ldg(skip_b + coutL);
                    float w0 = __ldg(skip_w + coutL * 3);
                    float w1 = __ldg(skip_w + coutL * 3 + 1);
                    float w2 = __ldg(skip_w + coutL * 3 + 2);
                    v0 += sb + xa0 * w0 + xa1 * w1 + xa2 * w2;
                    v1 += sb + xb0 * w0 + xb1 * w1 + xb2 * w2;
                    *(float2*)(out + (long)coutL * HW + o) = make_float2(v0, v1);
                }
                if (coutH < COUT) {
                    float sb = __ldg(skip_b + coutH);
                    float w0 = __ldg(skip_w + coutH * 3);
                    float w1 = __ldg(skip_w + coutH * 3 + 1);
                    float w2 = __ldg(skip_w + coutH * 3 + 2);
                    v2 += sb + xa0 * w0 + xa1 * w1 + xa2 * w2;
                    v3 += sb + xb0 * w0 + xb1 * w1 + xb2 * w2;
                    *(float2*)(out + (long)coutH * HW + o) = make_float2(v2, v3);
                }
            } else {
                *(float2*)(out + (long)coutL * HW + o) = make_float2(v0, v1);
                *(float2*)(out + (long)coutH * HW + o) = make_float2(v2, v3);
            }
        }
    }
}

// ---------------------------------------------------------------------------
// Fused 1x1 convs: K = kw*a, V = vw*a, Q = qw*b. One thread per pixel.
// ---------------------------------------------------------------------------
__global__ void __launch_bounds__(256) qkv_kernel(
    const float* __restrict__ a, const float* __restrict__ b,
    const float* __restrict__ qw, const float* __restrict__ qb,
    const float* __restrict__ kw, const float* __restrict__ kb,
    const float* __restrict__ vw, const float* __restrict__ vb,
    float* __restrict__ Q, float* __restrict__ K, float* __restrict__ V)
{
    __shared__ float s_qw[576], s_kw[576], s_vw[576];
    __shared__ float s_qb[24], s_kb[24], s_vb[24];
    for (int i = threadIdx.x; i < 576; i += 256) {
        int co = i % 24, ci = i / 24;
        s_qw[i] = qw[co * 24 + ci];
        s_kw[i] = kw[co * 24 + ci];
        s_vw[i] = vw[co * 24 + ci];
    }
    if (threadIdx.x < 24) {
        s_qb[threadIdx.x] = qb[threadIdx.x];
        s_kb[threadIdx.x] = kb[threadIdx.x];
        s_vb[threadIdx.x] = vb[threadIdx.x];
    }
    __syncthreads();

    const int idx = blockIdx.x * 256 + threadIdx.x;

    float iv[24];
#pragma unroll
    for (int c = 0; c < 24; c++) iv[c] = a[c * HW + idx];

    float acc[24];
#pragma unroll
    for (int c = 0; c < 24; c++) acc[c] = s_kb[c];
#pragma unroll
    for (int ci = 0; ci < 24; ci++) {
        float v = iv[ci];
        const float* wp = s_kw + ci * 24;
#pragma unroll
        for (int c = 0; c < 24; c++) acc[c] = fmaf(v, wp[c], acc[c]);
    }
#pragma unroll
    for (int c = 0; c < 24; c++) K[c * HW + idx] = acc[c];

#pragma unroll
    for (int c = 0; c < 24; c++) acc[c] = s_vb[c];
#pragma unroll
    for (int ci = 0; ci < 24; ci++) {
        float v = iv[ci];
        const float* wp = s_vw + ci * 24;
#pragma unroll
        for (int c = 0; c < 24; c++) acc[c] = fmaf(v, wp[c], acc[c]);
    }
#pragma unroll
    for (int c = 0; c < 24; c++) V[c * HW + idx] = acc[c];

#pragma unroll
    for (int c = 0; c < 24; c++) iv[c] = b[c * HW + idx];
#pragma unroll
    for (int c = 0; c < 24; c++) acc[c] = s_qb[c];
#pragma unroll
    for (int ci = 0; ci < 24; ci++) {
        float v = iv[ci];
        const float* wp = s_qw + ci * 24;
#pragma unroll
        for (int c = 0; c < 24; c++) acc[c] = fmaf(v, wp[c], acc[c]);
    }
#pragma unroll
    for (int c = 0; c < 24; c++) Q[c * HW + idx] = acc[c];
}

// ---------------------------------------------------------------------------
// Local 7x7 attention (pad 3, zero-padded unfold => OOB score = 0, included
// in softmax; OOB V = 0). out[0:24] = y + a, out[24:48] = b.
// ---------------------------------------------------------------------------
__global__ void __launch_bounds__(256) attn_kernel(
    const float* __restrict__ Q, const float* __restrict__ K,
    const float* __restrict__ Vv, const float* __restrict__ a,
    const float* __restrict__ b, float* __restrict__ out)
{
    const int idx = blockIdx.x * 256 + threadIdx.x;
    const int y = idx >> 8;
    const int x = idx & 255;

    float q[24];
#pragma unroll
    for (int c = 0; c < 24; c++) q[c] = Q[c * HW + idx];

    const float scale = 0.20412414523193154f;  // 1/sqrt(24)
    float s[49];
#pragma unroll
    for (int p = 0; p < 49; p++) {
        const int ny = y + p / 7 - 3;
        const int nx = x + p % 7 - 3;
        float d = 0.f;
        if ((unsigned)ny < HGT && (unsigned)nx < WID) {
            const float* kp = K + ny * WID + nx;
#pragma unroll
            for (int c = 0; c < 24; c++) d = fmaf(q[c], __ldg(kp + c * HW), d);
        }
        s[p] = d * scale;
    }

    float m = s[0];
#pragma unroll
    for (int p = 1; p < 49; p++) m = fmaxf(m, s[p]);
    float sum = 0.f;
#pragma unroll
    for (int p = 0; p < 49; p++) {
        s[p] = __expf(s[p] - m);
        sum += s[p];
    }
    const float inv = 1.0f / sum;

    float acc[24];
#pragma unroll
    for (int c = 0; c < 24; c++) acc[c] = 0.f;
#pragma unroll
    for (int p = 0; p < 49; p++) {
        const int ny = y + p / 7 - 3;
        const int nx = x + p % 7 - 3;
        if ((unsigned)ny < HGT && (unsigned)nx < WID) {
            const float wgt = s[p] * inv;
            const float* vp = Vv + ny * WID + nx;
#pragma unroll
            for (int c = 0; c < 24; c++) acc[c] = fmaf(wgt, __ldg(vp + c * HW), acc[c]);
        }
    }

#pragma unroll
    for (int c = 0; c < 24; c++) out[c * HW + idx] = acc[c] + a[c * HW + idx];
#pragma unroll
    for (int c = 0; c < 24; c++) out[(24 + c) * HW + idx] = b[c * HW + idx];
}

// ---------------------------------------------------------------------------
extern "C" void kernel_launch(void* const* d_in, const int* in_sizes, int n_in,
                              void* d_out, int out_size)
{
    const float* x      = (const float*)d_in[0];
    const float* w0     = (const float*)d_in[1];
    const float* b0     = (const float*)d_in[2];
    const float* w1     = (const float*)d_in[3];
    const float* b1     = (const float*)d_in[4];
    const float* w2     = (const float*)d_in[5];
    const float* b2     = (const float*)d_in[6];
    const float* w3     = (const float*)d_in[7];
    const float* b3     = (const float*)d_in[8];
    const float* skip_w = (const float*)d_in[9];
    const float* skip_b = (const float*)d_in[10];
    const float* q_w    = (const float*)d_in[11];
    const float* q_b    = (const float*)d_in[12];
    const float* k_w    = (const float*)d_in[13];
    const float* k_b    = (const float*)d_in[14];
    const float* v_w    = (const float*)d_in[15];
    const float* v_b    = (const float*)d_in[16];
    float* out = (float*)d_out;

    float *h0, *h1, *ab, *Qp, *Kp, *Vp;
    unsigned* wa;
    cudaGetSymbolAddress((void**)&h0, g_h0);
    cudaGetSymbolAddress((void**)&h1, g_h1);
    cudaGetSymbolAddress((void**)&ab, g_ab);
    cudaGetSymbolAddress((void**)&Qp, g_Q);
    cudaGetSymbolAddress((void**)&Kp, g_K);
    cudaGetSymbolAddress((void**)&Vp, g_V);
    cudaGetSymbolAddress((void**)&wa, g_warr);

    // g_warr layout: conv0 @0 (3456), conv1 @3456 (20736), conv2 @24192 (20736),
    // conv3 @44928 (13824)
    arrange_w<3, 48, 1, 3><<<14, 256>>>(w0, wa);
    arrange_w<48, 48, 6, 3><<<81, 256>>>(w1, wa + 3456);
    arrange_w<48, 48, 6, 3><<<81, 256>>>(w2, wa + 24192);
    arrange_w<48, 24, 6, 2><<<54, 256>>>(w3, wa + 44928);

    const int sm_c0 = 324 * 20 * 4;   // 25920 B
    const int sm_c48 = 324 * 52 * 4;  // 67392 B
    cudaFuncSetAttribute((const void*)conv_mma<3, 8, 48, 1, 3, 20, false>,
                         cudaFuncAttributeMaxDynamicSharedMemorySize, sm_c0);
    cudaFuncSetAttribute((const void*)conv_mma<48, 48, 48, 6, 3, 52, false>,
                         cudaFuncAttributeMaxDynamicSharedMemorySize, sm_c48);
    cudaFuncSetAttribute((const void*)conv_mma<48, 48, 24, 6, 2, 52, true>,
                         cudaFuncAttributeMaxDynamicSharedMemorySize, sm_c48);

    dim3 g(16, 16, 2);
    // conv0: x(3ch) -> h0(48ch), relu
    conv_mma<3, 8, 48, 1, 3, 20, false><<<g, 256, sm_c0>>>(
        x, wa, b0, h0, 3L * HW, 48L * HW, nullptr, nullptr, nullptr);
    // conv1: h0 -> h1
    conv_mma<48, 48, 48, 6, 3, 52, false><<<g, 256, sm_c48>>>(
        h0, wa + 3456, b1, h1, 48L * HW, 48L * HW, nullptr, nullptr, nullptr);
    // conv2: h1 -> h0
    conv_mma<48, 48, 48, 6, 3, 52, false><<<g, 256, sm_c48>>>(
        h1, wa + 24192, b2, h0, 48L * HW, 48L * HW, nullptr, nullptr, nullptr);
    // conv3 + 1x1 skip: h0 -> ab
    conv_mma<48, 48, 24, 6, 2, 52, true><<<g, 256, sm_c48>>>(
        h0, wa + 44928, b3, ab, 48L * HW, 24L * HW, x, skip_w, skip_b);
    // Q/K/V 1x1 convs
    qkv_kernel<<<HW / 256, 256>>>(ab, ab + 24L * HW, q_w, q_b, k_w, k_b,
                                  v_w, v_b, Qp, Kp, Vp);
    // attention + residual + concat
    attn_kernel<<<HW / 256, 256>>>(Qp, Kp, Vp, ab, ab + 24L * HW, out);
}